// round 2
// baseline (speedup 1.0000x reference)
#include <cuda_runtime.h>
#include <math.h>

// ---------------- problem constants ----------------
#define NB   64
#define NL   1024
#define NT   65536        // NB*NL tokens
#define DM   1024
#define DS   256
#define NIN  28
#define NCL  10
#define LOGITS_OFF 640    // NB*NCL floats, activations follow

// ---------------- device scratch (static globals; no allocs) ----------------
__device__ float g_G [DS*DS];          // G = A^T
__device__ float g_G2[DS*DS];          // G^2
__device__ float g_GG[2*DS*DS];        // [G^4 ; G^8]
__device__ float g_M [DS*NIN];         // M = Bm @ W_in   (256x28)
__device__ float g_R [4*NIN*DS];       // R_b = M^T G^b   (4 x 28 x 256)
__device__ float g_bv[DS];
__device__ float g_bw[4*DS];           // bias prefix sums bv*(I+..+G^s)
__device__ float g_CT[DS*DM];          // C^T (256x1024)
__device__ float g_W [(size_t)NT*DS];  // level-1 conv out (64MB)
__device__ float g_S [(size_t)NT*DS];  // states (64MB)
__device__ float g_pooled[NB*DM];

// ---------------- tiny helpers ----------------
__global__ void kt_zero_pooled() {
    int i = blockIdx.x * blockDim.x + threadIdx.x;
    if (i < NB*DM) g_pooled[i] = 0.0f;
}

// dst (Cc x R) = src^T where src is (R x Cc), both row-major
__global__ void kt_transpose(float* __restrict__ dst, const float* __restrict__ src,
                             int R, int Cc) {
    int idx = blockIdx.x * blockDim.x + threadIdx.x;
    if (idx >= R*Cc) return;
    int r = idx / Cc, c = idx - r*Cc;
    dst[(size_t)c*R + r] = src[idx];
}

// generic tiled GEMM: C[MxN] = A[MxK] * B[KxN], row-major. 64x64 tile, BK=16.
__global__ void kt_tile_gemm(float* __restrict__ Cc, const float* __restrict__ Aa,
                             const float* __restrict__ Bb, int M, int N, int K) {
    __shared__ __align__(16) float A_sh[64*16];
    __shared__ __align__(16) float B_sh[16*64];
    int tx = threadIdx.x, ty = threadIdx.y;           // (16,16)
    int tid = ty*16 + tx;
    int n0 = blockIdx.x*64, m0 = blockIdx.y*64;
    float acc[4][4] = {};
    for (int k0 = 0; k0 < K; k0 += 16) {
        __syncthreads();
#pragma unroll
        for (int j = 0; j < 4; j++) {
            int e = j*256 + tid;
            int r  = e >> 4, kk = e & 15;
            A_sh[e] = (m0+r < M && k0+kk < K) ? Aa[(size_t)(m0+r)*K + k0+kk] : 0.f;
            int r2 = e >> 6, c2 = e & 63;
            B_sh[e] = (k0+r2 < K && n0+c2 < N) ? Bb[(size_t)(k0+r2)*N + n0+c2] : 0.f;
        }
        __syncthreads();
#pragma unroll
        for (int kk = 0; kk < 16; kk++) {
            float a[4], b[4];
#pragma unroll
            for (int r = 0; r < 4; r++) a[r] = A_sh[(ty*4+r)*16 + kk];
#pragma unroll
            for (int c = 0; c < 4; c++) b[c] = B_sh[kk*64 + tx*4 + c];
#pragma unroll
            for (int r = 0; r < 4; r++)
#pragma unroll
                for (int c = 0; c < 4; c++) acc[r][c] += a[r]*b[c];
        }
    }
#pragma unroll
    for (int r = 0; r < 4; r++)
#pragma unroll
        for (int c = 0; c < 4; c++) {
            int m = m0 + ty*4 + r, n = n0 + tx*4 + c;
            if (m < M && n < N) Cc[(size_t)m*N + n] = acc[r][c];
        }
}

// bv = Bm @ b_in  (one block of DS threads)
__global__ void kt_bv(const float* __restrict__ Bm, const float* __restrict__ b_in) {
    int c = threadIdx.x;
    float s = 0.f;
    for (int k = 0; k < DM; k++) s += Bm[(size_t)c*DM + k] * b_in[k];
    g_bv[c] = s;
}

// bias prefix chain: bw[s] = bv * (I + G + ... + G^s), s=0..3 (one block of DS threads)
__global__ void kt_bias() {
    __shared__ float cur[DS];
    int c = threadIdx.x;
    float v = g_bv[c];
    cur[c] = v;
    float accum = v;
    g_bw[c] = v;
    for (int s = 1; s < 4; s++) {
        __syncthreads();
        float nxt = 0.f;
#pragma unroll 8
        for (int k = 0; k < DS; k++) nxt += cur[k] * g_G[k*DS + c];
        __syncthreads();
        cur[c] = nxt;
        accum += nxt;
        g_bw[s*DS + c] = accum;
    }
}

// ---------------- level-1 conv: W_t = bw[min(l,3)] + sum_{b<4} x_{t-b} R_b ----
// grid 4096 (1024 token-tiles x 4 col-tiles), block (16,16).
__global__ __launch_bounds__(256, 2) void kt_W(const float* __restrict__ x) {
    __shared__ __align__(16) float R_sh[112*64];  // 28KB
    __shared__ __align__(16) float X_sh[67*28];   // 7.5KB
    int tx = threadIdx.x, ty = threadIdx.y;
    int tid = ty*16 + tx;
    int mblk = blockIdx.x >> 2, nblk = blockIdx.x & 3;
    int t0 = mblk*64, n0 = nblk*64;
    int bbase = t0 & ~(NL-1);

    for (int e = tid; e < 112*64; e += 256) {
        int row = e >> 6, col = e & 63;
        R_sh[e] = g_R[row*DS + n0 + col];
    }
    for (int e = tid; e < 67*28; e += 256) {
        int row = e / 28, col = e - row*28;
        int gt = t0 - 3 + row;
        X_sh[e] = (gt >= bbase) ? x[(size_t)gt*NIN + col] : 0.f;
    }
    __syncthreads();

    int l0 = t0 & (NL-1);
    float4 acc[4];
#pragma unroll
    for (int r = 0; r < 4; r++) {
        int l = l0 + ty*4 + r;
        int sel = l < 3 ? l : 3;
        acc[r] = *(const float4*)&g_bw[sel*DS + n0 + tx*4];
    }
#pragma unroll
    for (int i = 0; i < 28; i++) {
        float xv[7];
#pragma unroll
        for (int m = 0; m < 7; m++) xv[m] = X_sh[(ty*4 + m)*28 + i];
#pragma unroll
        for (int bb = 0; bb < 4; bb++) {
            const float4 rv = *(const float4*)&R_sh[(bb*28 + i)*64 + tx*4];
#pragma unroll
            for (int r = 0; r < 4; r++) {
                float a = xv[r + 3 - bb];
                acc[r].x += a*rv.x; acc[r].y += a*rv.y;
                acc[r].z += a*rv.z; acc[r].w += a*rv.w;
            }
        }
    }
#pragma unroll
    for (int r = 0; r < 4; r++)
        *(float4*)&g_W[(size_t)(t0 + ty*4 + r)*DS + n0 + tx*4] = acc[r];
}

// ---------------- level-2: S_t = W_t + W_{t-4} G4 + W_{t-8} G8 ----------------
// grid 1024 (64-token tiles, full 256 cols), block (32,8).
__global__ __launch_bounds__(256, 2) void kt_S() {
    __shared__ __align__(16) float A_sh[64*16];   // 4KB
    __shared__ __align__(16) float B_sh[16*256];  // 16KB
    int tx = threadIdx.x, ty = threadIdx.y;       // (32,8)
    int tid = ty*32 + tx;
    int t0 = blockIdx.x * 64;

    float4 acc[8][2];
#pragma unroll
    for (int r = 0; r < 8; r++) {
        size_t base = (size_t)(t0 + ty*8 + r)*DS + tx*4;
        acc[r][0] = *(const float4*)&g_W[base];
        acc[r][1] = *(const float4*)&g_W[base + 128];
    }
#pragma unroll
    for (int ph = 0; ph < 2; ph++) {
        int shift = ph ? 8 : 4;
        size_t gbase = (size_t)ph * DS * DS;
        for (int kc = 0; kc < DS; kc += 16) {
            __syncthreads();
#pragma unroll
            for (int j = 0; j < 4; j++) {
                int e = j*256 + tid;
                int r = e >> 4, kk = e & 15;
                int t = t0 + r;
                A_sh[e] = ((t & (NL-1)) >= shift)
                          ? g_W[(size_t)(t - shift)*DS + kc + kk] : 0.f;
            }
#pragma unroll
            for (int j = 0; j < 16; j++)
                B_sh[j*256 + tid] = g_GG[gbase + (size_t)kc*DS + j*256 + tid];
            __syncthreads();
#pragma unroll
            for (int kk = 0; kk < 16; kk++) {
                const float4 b0 = *(const float4*)&B_sh[kk*256 + tx*4];
                const float4 b1 = *(const float4*)&B_sh[kk*256 + tx*4 + 128];
#pragma unroll
                for (int r = 0; r < 8; r++) {
                    float a = A_sh[(ty*8 + r)*16 + kk];
                    acc[r][0].x += a*b0.x; acc[r][0].y += a*b0.y;
                    acc[r][0].z += a*b0.z; acc[r][0].w += a*b0.w;
                    acc[r][1].x += a*b1.x; acc[r][1].y += a*b1.y;
                    acc[r][1].z += a*b1.z; acc[r][1].w += a*b1.w;
                }
            }
        }
    }
#pragma unroll
    for (int r = 0; r < 8; r++) {
        size_t base = (size_t)(t0 + ty*8 + r)*DS + tx*4;
        *(float4*)&g_S[base]       = acc[r][0];
        *(float4*)&g_S[base + 128] = acc[r][1];
    }
}

__device__ __forceinline__ float gelu_exact(float y) {
    return 0.5f * y * (1.0f + erff(y * 0.70710678118654752f));
}
__device__ __forceinline__ float fixv(float v) {
    if (isnan(v)) return 0.f;
    if (isinf(v)) return v > 0.f ? 1000000.0f : -1000000.0f;
    return v;
}

// ---------------- Y = S C^T, fused GELU + LayerNorm + activation store --------
// grid 4096 (16-token tiles x full 1024 cols), block (128,2). 8 rows x 8 cols/thread.
__global__ __launch_bounds__(256, 2) void kt_Y(const float* __restrict__ gamma,
                                               const float* __restrict__ beta,
                                               float* __restrict__ out) {
    __shared__ __align__(16) float smem[12288];   // 48KB
    float* S_sh  = smem;        // 16x256
    float* CT_sh = smem + 4096; // 8x1024
    const int tx = threadIdx.x;   // 0..127
    const int ty = threadIdx.y;   // 0..1
    const int tid = ty*128 + tx;
    const int t0 = blockIdx.x * 16;

#pragma unroll
    for (int j = 0; j < 16; j++)
        S_sh[j*256 + tid] = g_S[(size_t)t0*DS + j*256 + tid];

    float4 acc0[8], acc1[8];
#pragma unroll
    for (int r = 0; r < 8; r++) { acc0[r] = make_float4(0,0,0,0); acc1[r] = make_float4(0,0,0,0); }

    for (int kc = 0; kc < DS; kc += 8) {
        __syncthreads();
#pragma unroll
        for (int j = 0; j < 32; j++)
            CT_sh[j*256 + tid] = g_CT[(size_t)kc*DM + j*256 + tid];
        __syncthreads();
#pragma unroll
        for (int k = 0; k < 8; k++) {
            const float4 c0 = *(const float4*)&CT_sh[k*DM + tx*4];
            const float4 c1 = *(const float4*)&CT_sh[k*DM + tx*4 + 512];
#pragma unroll
            for (int r = 0; r < 8; r++) {
                float a = S_sh[(ty*8 + r)*256 + kc + k];
                acc0[r].x += a*c0.x; acc0[r].y += a*c0.y;
                acc0[r].z += a*c0.z; acc0[r].w += a*c0.w;
                acc1[r].x += a*c1.x; acc1[r].y += a*c1.y;
                acc1[r].z += a*c1.z; acc1[r].w += a*c1.w;
            }
        }
    }
    __syncthreads();   // done reading S_sh/CT_sh; smem reused below

    // GELU in place + per-row partial sums for LayerNorm
    float s1[8], s2[8];
#pragma unroll
    for (int r = 0; r < 8; r++) {
        acc0[r].x = gelu_exact(acc0[r].x); acc0[r].y = gelu_exact(acc0[r].y);
        acc0[r].z = gelu_exact(acc0[r].z); acc0[r].w = gelu_exact(acc0[r].w);
        acc1[r].x = gelu_exact(acc1[r].x); acc1[r].y = gelu_exact(acc1[r].y);
        acc1[r].z = gelu_exact(acc1[r].z); acc1[r].w = gelu_exact(acc1[r].w);
        s1[r] = acc0[r].x+acc0[r].y+acc0[r].z+acc0[r].w
              + acc1[r].x+acc1[r].y+acc1[r].z+acc1[r].w;
        s2[r] = acc0[r].x*acc0[r].x+acc0[r].y*acc0[r].y+acc0[r].z*acc0[r].z+acc0[r].w*acc0[r].w
              + acc1[r].x*acc1[r].x+acc1[r].y*acc1[r].y+acc1[r].z*acc1[r].z+acc1[r].w*acc1[r].w;
    }
#pragma unroll
    for (int off = 16; off > 0; off >>= 1) {
#pragma unroll
        for (int r = 0; r < 8; r++) {
            s1[r] += __shfl_down_sync(0xffffffffu, s1[r], off);
            s2[r] += __shfl_down_sync(0xffffffffu, s2[r], off);
        }
    }
    float* rsum = smem;         // 16 rows x 4 warp-partials
    float* rsq  = smem + 64;
    int wq = tx >> 5;           // warp index within ty (0..3)
    if ((tx & 31) == 0) {
#pragma unroll
        for (int r = 0; r < 8; r++) {
            rsum[(ty*8 + r)*4 + wq] = s1[r];
            rsq [(ty*8 + r)*4 + wq] = s2[r];
        }
    }
    __syncthreads();

    const float4 g0  = *(const float4*)&gamma[tx*4];
    const float4 g1  = *(const float4*)&gamma[tx*4 + 512];
    const float4 be0 = *(const float4*)&beta[tx*4];
    const float4 be1 = *(const float4*)&beta[tx*4 + 512];

#pragma unroll
    for (int r = 0; r < 8; r++) {
        int row = ty*8 + r;
        float sum = rsum[row*4]+rsum[row*4+1]+rsum[row*4+2]+rsum[row*4+3];
        float sq  = rsq [row*4]+rsq [row*4+1]+rsq [row*4+2]+rsq [row*4+3];
        float mu  = sum * (1.0f/DM);
        float var = sq * (1.0f/DM) - mu*mu;
        float rstd = rsqrtf(var + 1e-5f);

        float4 n0, n1;
        n0.x = fixv((acc0[r].x - mu)*rstd*g0.x + be0.x);
        n0.y = fixv((acc0[r].y - mu)*rstd*g0.y + be0.y);
        n0.z = fixv((acc0[r].z - mu)*rstd*g0.z + be0.z);
        n0.w = fixv((acc0[r].w - mu)*rstd*g0.w + be0.w);
        n1.x = fixv((acc1[r].x - mu)*rstd*g1.x + be1.x);
        n1.y = fixv((acc1[r].y - mu)*rstd*g1.y + be1.y);
        n1.z = fixv((acc1[r].z - mu)*rstd*g1.z + be1.z);
        n1.w = fixv((acc1[r].w - mu)*rstd*g1.w + be1.w);

        size_t base = (size_t)LOGITS_OFF + (size_t)(t0 + row)*DM + tx*4;
        *(float4*)&out[base]       = n0;
        *(float4*)&out[base + 512] = n1;
    }
}

// ---------------- pooled = mean over L of activations --------------------------
// grid (NB, 8): each block sums 128 l-rows; block 256 threads, 4 cols each.
__global__ void kt_pool(const float* __restrict__ out) {
    int b = blockIdx.x;
    int l0 = blockIdx.y * 128;
    int tid = threadIdx.x;
    float4 acc = make_float4(0,0,0,0);
    const float* base = out + LOGITS_OFF + (size_t)b*NL*DM + (size_t)l0*DM + tid*4;
    for (int l = 0; l < 128; l++) {
        float4 v = *(const float4*)(base + (size_t)l*DM);
        acc.x += v.x; acc.y += v.y; acc.z += v.z; acc.w += v.w;
    }
    const float inv = 1.0f / (float)NL;
    float* p = &g_pooled[b*DM + tid*4];
    atomicAdd(p+0, acc.x*inv);
    atomicAdd(p+1, acc.y*inv);
    atomicAdd(p+2, acc.z*inv);
    atomicAdd(p+3, acc.w*inv);
}

// ---------------- logits = pooled @ W_fc^T + b_fc ------------------------------
// grid NB, block 32 (one warp per batch row).
__global__ void kt_logits(const float* __restrict__ W_fc, const float* __restrict__ b_fc,
                          float* __restrict__ out) {
    int b = blockIdx.x;
    int lane = threadIdx.x;
    for (int c = 0; c < NCL; c++) {
        float s = 0.f;
        for (int d = lane; d < DM; d += 32)
            s += g_pooled[b*DM + d] * W_fc[c*DM + d];
#pragma unroll
        for (int off = 16; off > 0; off >>= 1)
            s += __shfl_down_sync(0xffffffffu, s, off);
        if (lane == 0) out[b*NCL + c] = s + b_fc[c];
    }
}

// ---------------- launch ----------------
extern "C" void kernel_launch(void* const* d_in, const int* in_sizes, int n_in,
                              void* d_out, int out_size) {
    const float* x     = (const float*)d_in[0];
    const float* W_in  = (const float*)d_in[1];
    const float* b_in  = (const float*)d_in[2];
    const float* A     = (const float*)d_in[3];
    const float* Bm    = (const float*)d_in[4];
    const float* C     = (const float*)d_in[5];
    const float* gamma = (const float*)d_in[6];
    const float* beta  = (const float*)d_in[7];
    const float* W_fc  = (const float*)d_in[8];
    const float* b_fc  = (const float*)d_in[9];
    float* out = (float*)d_out;

    float *pG, *pG2, *pGG, *pM, *pR, *pCT;
    cudaGetSymbolAddress((void**)&pG,  g_G);
    cudaGetSymbolAddress((void**)&pG2, g_G2);
    cudaGetSymbolAddress((void**)&pGG, g_GG);
    cudaGetSymbolAddress((void**)&pM,  g_M);
    cudaGetSymbolAddress((void**)&pR,  g_R);
    cudaGetSymbolAddress((void**)&pCT, g_CT);

    dim3 blk16(16,16);

    // precompute (tiny, rerun every call: deterministic)
    kt_transpose<<<DS*DS/256, 256>>>(pG, A, DS, DS);                 // G = A^T
    kt_transpose<<<DS*DM/256, 256>>>(pCT, C, DM, DS);                // CT = C^T
    kt_tile_gemm<<<dim3(1,4), blk16>>>(pM, Bm, W_in, DS, NIN, DM);   // M = Bm@W_in
    kt_tile_gemm<<<dim3(4,4), blk16>>>(pG2, pG, pG, DS, DS, DS);     // G2
    kt_tile_gemm<<<dim3(4,4), blk16>>>(pGG, pG2, pG2, DS, DS, DS);   // G4
    kt_tile_gemm<<<dim3(4,4), blk16>>>(pGG + DS*DS, pGG, pGG, DS, DS, DS); // G8
    kt_transpose<<<28, 256>>>(pR, pM, DS, NIN);                      // R0 = M^T
    kt_tile_gemm<<<dim3(4,1), blk16>>>(pR + 1*NIN*DS, pR, pG,  NIN, DS, DS); // R1
    kt_tile_gemm<<<dim3(4,1), blk16>>>(pR + 2*NIN*DS, pR, pG2, NIN, DS, DS); // R2
    kt_tile_gemm<<<dim3(4,1), blk16>>>(pR + 3*NIN*DS, pR + 1*NIN*DS, pG2, NIN, DS, DS); // R3
    kt_bv<<<1, DS>>>(Bm, b_in);
    kt_bias<<<1, DS>>>();
    kt_zero_pooled<<<NB*DM/256, 256>>>();

    // main pipeline
    kt_W<<<4096, blk16>>>(x);
    kt_S<<<1024, dim3(32,8)>>>();
    kt_Y<<<4096, dim3(128,2)>>>(gamma, beta, out);
    kt_pool<<<dim3(NB,8), 256>>>(out);
    kt_logits<<<NB, 32>>>(W_fc, b_fc, out);
}

// round 3
// speedup vs baseline: 1.1113x; 1.1113x over previous
#include <cuda_runtime.h>
#include <math.h>

// ---------------- problem constants ----------------
#define NB   64
#define NL   1024
#define NT   65536        // NB*NL tokens
#define DM   1024
#define DS   256
#define NIN  28
#define NCL  10
#define NTAP 12
#define KTOT (NTAP*NIN)   // 336
#define MT   32           // token rows per block in kt_Y
#define KP   8            // k-panel size in kt_Y
#define LOGITS_OFF 640    // NB*NCL floats, activations follow

// ---------------- device scratch ----------------
__device__ float g_G [DS*DS];          // G = A^T
__device__ float g_G2[DS*DS];
__device__ float g_G4[DS*DS];
__device__ float g_M [DS*NIN];         // M = Bm @ W_in
__device__ float g_R [NTAP*NIN*DS];    // R_b = M^T G^b   (336 x 256)
__device__ float g_CT[DS*DM];          // C^T (256x1024)
__device__ float g_Q [KTOT*DM];        // Q = R @ C^T (336 x 1024)
__device__ float g_bv[DS];
__device__ float g_bw[NTAP*DS];        // bv*(I+..+G^s), s=0..11
__device__ float g_qb[NTAP*DM];        // bw @ C^T
__device__ float g_pooled[NB*DM];

// ---------------- f32x2 helpers ----------------
#define FFMA2(d,a,b) asm("fma.rn.f32x2 %0, %1, %2, %0;" : "+l"(d) : "l"(a), "l"(b))
__device__ __forceinline__ unsigned long long pack_dup(float v) {
    unsigned long long p;
    asm("mov.b64 %0, {%1, %1};" : "=l"(p) : "f"(v));
    return p;
}
__device__ __forceinline__ void unpack2(float& lo, float& hi, unsigned long long p) {
    asm("mov.b64 {%0, %1}, %2;" : "=f"(lo), "=f"(hi) : "l"(p));
}
__device__ __forceinline__ unsigned long long pack2(float lo, float hi) {
    unsigned long long p;
    asm("mov.b64 %0, {%1, %2};" : "=l"(p) : "f"(lo), "f"(hi));
    return p;
}

// ---------------- tiny helpers ----------------
__global__ void kt_zero_pooled() {
    int i = blockIdx.x * blockDim.x + threadIdx.x;
    if (i < NB*DM) g_pooled[i] = 0.0f;
}

// dst (Cc x R) = src^T where src is (R x Cc), both row-major
__global__ void kt_transpose(float* __restrict__ dst, const float* __restrict__ src,
                             int R, int Cc) {
    int idx = blockIdx.x * blockDim.x + threadIdx.x;
    if (idx >= R*Cc) return;
    int r = idx / Cc, c = idx - r*Cc;
    dst[(size_t)c*R + r] = src[idx];
}

// GEMM C[MxN] = A[MxK]*B[KxN], row-major, 32x32 tiles (good occupancy for small mats)
__global__ void kt_gemm32(float* __restrict__ Cc, const float* __restrict__ Aa,
                          const float* __restrict__ Bb, int M, int N, int K) {
    __shared__ float As[32][33];
    __shared__ float Bs[32][33];
    int tx = threadIdx.x & 15, ty = threadIdx.x >> 4;
    int n0 = blockIdx.x*32, m0 = blockIdx.y*32;
    float a00=0.f,a01=0.f,a10=0.f,a11=0.f;
    for (int k0 = 0; k0 < K; k0 += 32) {
#pragma unroll
        for (int j = 0; j < 4; j++) {
            int e = j*256 + threadIdx.x;
            int r = e >> 5, c = e & 31;
            As[r][c] = (m0+r < M && k0+c < K) ? Aa[(size_t)(m0+r)*K + k0+c] : 0.f;
            Bs[r][c] = (k0+r < K && n0+c < N) ? Bb[(size_t)(k0+r)*N + n0+c] : 0.f;
        }
        __syncthreads();
#pragma unroll
        for (int kk = 0; kk < 32; kk++) {
            float x0 = As[ty*2][kk],  x1 = As[ty*2+1][kk];
            float y0 = Bs[kk][tx*2],  y1 = Bs[kk][tx*2+1];
            a00 += x0*y0; a01 += x0*y1; a10 += x1*y0; a11 += x1*y1;
        }
        __syncthreads();
    }
    int m = m0 + ty*2, n = n0 + tx*2;
    if (m   < M && n   < N) Cc[(size_t)m*N + n]       = a00;
    if (m   < M && n+1 < N) Cc[(size_t)m*N + n+1]     = a01;
    if (m+1 < M && n   < N) Cc[(size_t)(m+1)*N + n]   = a10;
    if (m+1 < M && n+1 < N) Cc[(size_t)(m+1)*N + n+1] = a11;
}

// bv = Bm @ b_in
__global__ void kt_bv(const float* __restrict__ Bm, const float* __restrict__ b_in) {
    int c = threadIdx.x;
    float s = 0.f;
    for (int k = 0; k < DM; k++) s += Bm[(size_t)c*DM + k] * b_in[k];
    g_bv[c] = s;
}

// bw[s] = bv * (I + G + ... + G^s), s=0..11
__global__ void kt_bias() {
    __shared__ float cur[DS];
    int c = threadIdx.x;
    float v = g_bv[c];
    cur[c] = v;
    float accum = v;
    g_bw[c] = v;
    for (int s = 1; s < NTAP; s++) {
        __syncthreads();
        float nxt = 0.f;
#pragma unroll 8
        for (int k = 0; k < DS; k++) nxt += cur[k] * g_G[k*DS + c];
        __syncthreads();
        cur[c] = nxt;
        accum += nxt;
        g_bw[s*DS + c] = accum;
    }
}

__device__ __forceinline__ float gelu_exact(float y) {
    return 0.5f * y * (1.0f + erff(y * 0.70710678118654752f));
}
__device__ __forceinline__ float fixv(float v) {
    if (isnan(v)) return 0.f;
    if (isinf(v)) return v > 0.f ? 1000000.0f : -1000000.0f;
    return v;
}

// ================= fused main kernel =================
// Y[t][c] = sum_k Xtilde[t][k]*Q[k][c] + qb[s(t)][c], then GELU + LN + store + pool.
// grid 2048 (32-token tiles), block 256. Per thread: 32 rows x 4 cols (f32x2-packed).
// smem: A2 (X dup pairs, 84KB) + Q double-buffer (64KB) + reductions.
#define SMEM_Y_FLOATS (MT*KTOT*2 + 2*KP*DM + 576)

__global__ __launch_bounds__(256, 1) void kt_Y(const float* __restrict__ x,
                                               const float* __restrict__ gamma,
                                               const float* __restrict__ beta,
                                               float* __restrict__ out) {
    extern __shared__ float sm[];
    unsigned long long* A2 = (unsigned long long*)sm;    // [MT*KTOT] u64 dup pairs
    float* Qs  = sm + MT*KTOT*2;                          // [2][KP][DM]
    float* red = Qs + 2*KP*DM;                            // rsum[256] rsq[256] mu[32] rs[32]
    float* rsum = red, *rsq = red + 256, *mu_s = red + 512, *rs_s = red + 544;

    const int tid = threadIdx.x;
    const int lane = tid & 31, warp = tid >> 5;
    const int t0 = blockIdx.x * MT;
    const int bbase = t0 & ~(NL-1);
    const int l0 = t0 & (NL-1);

    // ---- stage Xtilde (duplicated f32 pairs) ----
    for (int e = tid; e < MT*KTOT; e += 256) {
        int r = e / KTOT, k = e - r*KTOT;
        int b = k / NIN,  i = k - b*NIN;
        int t = t0 + r - b;
        float v = (t >= bbase) ? x[(size_t)t*NIN + i] : 0.f;
        A2[e] = pack_dup(v);
    }

    unsigned long long acc[MT][2];
#pragma unroll
    for (int r = 0; r < MT; r++) { acc[r][0] = 0ull; acc[r][1] = 0ull; }

    // prologue: load panel 0 (thread tid holds col-quad tid of each of KP rows)
    float4 st[KP];
#pragma unroll
    for (int j = 0; j < KP; j++)
        st[j] = *(const float4*)&g_Q[(size_t)j*DM + tid*4];
    __syncthreads();   // A2 visible

    const int NPANEL = KTOT / KP;  // 42
    for (int p = 0; p < NPANEL; p++) {
        float* Qb = Qs + (p & 1) * (KP*DM);
#pragma unroll
        for (int j = 0; j < KP; j++)
            *(float4*)&Qb[j*DM + tid*4] = st[j];
        __syncthreads();
        if (p + 1 < NPANEL) {
            int gk = (p+1) * KP;
#pragma unroll
            for (int j = 0; j < KP; j++)
                st[j] = *(const float4*)&g_Q[(size_t)(gk+j)*DM + tid*4];
        }
        int gk0 = p * KP;
#pragma unroll
        for (int kk = 0; kk < KP; kk += 2) {
            ulonglong2 q0 = *(const ulonglong2*)&Qb[kk*DM + tid*4];
            ulonglong2 q1 = *(const ulonglong2*)&Qb[(kk+1)*DM + tid*4];
            int kg = gk0 + kk;
#pragma unroll
            for (int r = 0; r < MT; r++) {
                ulonglong2 av = *(const ulonglong2*)&A2[r*KTOT + kg];
                FFMA2(acc[r][0], av.x, q0.x);
                FFMA2(acc[r][1], av.x, q0.y);
                FFMA2(acc[r][0], av.y, q1.x);
                FFMA2(acc[r][1], av.y, q1.y);
            }
        }
    }
    __syncthreads();

    // ---- epilogue pass 1: qbias + GELU + row partial sums ----
    const bool steady = (l0 >= NTAP - 1);
    float4 qv_st;
    if (steady) qv_st = *(const float4*)&g_qb[(NTAP-1)*DM + tid*4];
#pragma unroll
    for (int r = 0; r < MT; r++) {
        float4 qv = qv_st;
        if (!steady) {
            int l = l0 + r;
            int s = l < NTAP-1 ? l : NTAP-1;
            qv = *(const float4*)&g_qb[s*DM + tid*4];
        }
        float f0, f1, f2, f3;
        unpack2(f0, f1, acc[r][0]);
        unpack2(f2, f3, acc[r][1]);
        f0 = gelu_exact(f0 + qv.x); f1 = gelu_exact(f1 + qv.y);
        f2 = gelu_exact(f2 + qv.z); f3 = gelu_exact(f3 + qv.w);
        acc[r][0] = pack2(f0, f1);
        acc[r][1] = pack2(f2, f3);
        float s1 = f0 + f1 + f2 + f3;
        float s2 = f0*f0 + f1*f1 + f2*f2 + f3*f3;
#pragma unroll
        for (int off = 16; off > 0; off >>= 1) {
            s1 += __shfl_down_sync(0xffffffffu, s1, off);
            s2 += __shfl_down_sync(0xffffffffu, s2, off);
        }
        if (lane == 0) { rsum[r*8 + warp] = s1; rsq[r*8 + warp] = s2; }
    }
    __syncthreads();
    if (tid < MT) {
        float su = 0.f, sq = 0.f;
#pragma unroll
        for (int w = 0; w < 8; w++) { su += rsum[tid*8 + w]; sq += rsq[tid*8 + w]; }
        float mu = su * (1.0f/DM);
        float var = sq * (1.0f/DM) - mu*mu;
        mu_s[tid] = mu;
        rs_s[tid] = rsqrtf(var + 1e-5f);
    }
    __syncthreads();

    // ---- epilogue pass 2: normalize, store, pool ----
    const float4 gg = *(const float4*)&gamma[tid*4];
    const float4 bb = *(const float4*)&beta[tid*4];
    float p0 = 0.f, p1 = 0.f, p2 = 0.f, p3 = 0.f;
#pragma unroll
    for (int r = 0; r < MT; r++) {
        float mu = mu_s[r], rstd = rs_s[r];
        float f0, f1, f2, f3;
        unpack2(f0, f1, acc[r][0]);
        unpack2(f2, f3, acc[r][1]);
        float4 nv;
        nv.x = fixv((f0 - mu)*rstd*gg.x + bb.x);
        nv.y = fixv((f1 - mu)*rstd*gg.y + bb.y);
        nv.z = fixv((f2 - mu)*rstd*gg.z + bb.z);
        nv.w = fixv((f3 - mu)*rstd*gg.w + bb.w);
        *(float4*)&out[(size_t)LOGITS_OFF + (size_t)(t0 + r)*DM + tid*4] = nv;
        p0 += nv.x; p1 += nv.y; p2 += nv.z; p3 += nv.w;
    }
    const float inv = 1.0f / (float)NL;
    float* pp = &g_pooled[(t0 >> 10)*DM + tid*4];
    atomicAdd(pp+0, p0*inv);
    atomicAdd(pp+1, p1*inv);
    atomicAdd(pp+2, p2*inv);
    atomicAdd(pp+3, p3*inv);
}

// ---------------- logits = pooled @ W_fc^T + b_fc ----------------
__global__ void kt_logits(const float* __restrict__ W_fc, const float* __restrict__ b_fc,
                          float* __restrict__ out) {
    int b = blockIdx.x;
    int lane = threadIdx.x;
    for (int c = 0; c < NCL; c++) {
        float s = 0.f;
        for (int d = lane; d < DM; d += 32)
            s += g_pooled[b*DM + d] * W_fc[c*DM + d];
#pragma unroll
        for (int off = 16; off > 0; off >>= 1)
            s += __shfl_down_sync(0xffffffffu, s, off);
        if (lane == 0) out[b*NCL + c] = s + b_fc[c];
    }
}

// ---------------- launch ----------------
extern "C" void kernel_launch(void* const* d_in, const int* in_sizes, int n_in,
                              void* d_out, int out_size) {
    const float* x     = (const float*)d_in[0];
    const float* W_in  = (const float*)d_in[1];
    const float* b_in  = (const float*)d_in[2];
    const float* A     = (const float*)d_in[3];
    const float* Bm    = (const float*)d_in[4];
    const float* C     = (const float*)d_in[5];
    const float* gamma = (const float*)d_in[6];
    const float* beta  = (const float*)d_in[7];
    const float* W_fc  = (const float*)d_in[8];
    const float* b_fc  = (const float*)d_in[9];
    float* out = (float*)d_out;

    float *pG, *pG2, *pG4, *pM, *pR, *pCT, *pQ, *pBW, *pQB;
    cudaGetSymbolAddress((void**)&pG,  g_G);
    cudaGetSymbolAddress((void**)&pG2, g_G2);
    cudaGetSymbolAddress((void**)&pG4, g_G4);
    cudaGetSymbolAddress((void**)&pM,  g_M);
    cudaGetSymbolAddress((void**)&pR,  g_R);
    cudaGetSymbolAddress((void**)&pCT, g_CT);
    cudaGetSymbolAddress((void**)&pQ,  g_Q);
    cudaGetSymbolAddress((void**)&pBW, g_bw);
    cudaGetSymbolAddress((void**)&pQB, g_qb);

    static int smem_set = 0;
    if (!smem_set) {
        cudaFuncSetAttribute(kt_Y, cudaFuncAttributeMaxDynamicSharedMemorySize,
                             SMEM_Y_FLOATS * 4);
        smem_set = 1;
    }

    // ---- precompute (tiny, deterministic, rerun every call) ----
    kt_transpose<<<DS*DS/256, 256>>>(pG, A, DS, DS);               // G = A^T
    kt_transpose<<<DM*DS/256, 256>>>(pCT, C, DM, DS);              // CT = C^T
    kt_gemm32<<<dim3(1,8), 256>>>(pM, Bm, W_in, DS, NIN, DM);      // M = Bm@W_in
    kt_transpose<<<DS*NIN/256 + 1, 256>>>(pR, pM, DS, NIN);        // R0 = M^T
    kt_gemm32<<<dim3(8,8), 256>>>(pG2, pG, pG, DS, DS, DS);        // G2
    kt_gemm32<<<dim3(8,8), 256>>>(pG4, pG2, pG2, DS, DS, DS);      // G4
    kt_gemm32<<<dim3(8,1), 256>>>(pR + 1*NIN*DS, pR, pG,  NIN, DS, DS);          // R1
    kt_gemm32<<<dim3(8,1), 256>>>(pR + 2*NIN*DS, pR, pG2, NIN, DS, DS);          // R2
    kt_gemm32<<<dim3(8,1), 256>>>(pR + 3*NIN*DS, pR + 1*NIN*DS, pG2, NIN, DS, DS); // R3
    kt_gemm32<<<dim3(8,4), 256>>>(pR + 4*NIN*DS, pR, pG4, 4*NIN, DS, DS);        // R4..7
    kt_gemm32<<<dim3(8,4), 256>>>(pR + 8*NIN*DS, pR + 4*NIN*DS, pG4, 4*NIN, DS, DS); // R8..11
    kt_gemm32<<<dim3(32,11), 256>>>(pQ, pR, pCT, KTOT, DM, DS);    // Q = R @ CT
    kt_bv<<<1, DS>>>(Bm, b_in);
    kt_bias<<<1, DS>>>();
    kt_gemm32<<<dim3(32,1), 256>>>(pQB, pBW, pCT, NTAP, DM, DS);   // qb = bw @ CT
    kt_zero_pooled<<<NB*DM/256, 256>>>();

    // ---- fused main + logits ----
    kt_Y<<<NT/MT, 256, SMEM_Y_FLOATS*4>>>(x, gamma, beta, out);
    kt_logits<<<NB, 32>>>(W_fc, b_fc, out);
}

// round 5
// speedup vs baseline: 1.6953x; 1.5255x over previous
#include <cuda_runtime.h>
#include <cuda_bf16.h>
#include <math.h>
#include <stdint.h>

// ---------------- problem constants ----------------
#define NB   64
#define NL   1024
#define NT   65536        // NB*NL tokens
#define DM   1024
#define DS   256
#define NIN  28
#define NCL  10
#define NTAP 12
#define KTOT (NTAP*NIN)   // 336
#define KPAD 352          // padded K (11 chunks of 32)
#define NCHUNK 33         // 3 passes x 11 chunks
#define LOGITS_OFF 640    // NB*NCL floats, activations follow

// ---------------- device scratch ----------------
__device__ float g_G [DS*DS];
__device__ float g_G2[DS*DS];
__device__ float g_G4[DS*DS];
__device__ float g_M [DS*NIN];
__device__ float g_R [NTAP*NIN*DS];      // 336 x 256
__device__ float g_CT[DS*DM];
__device__ float g_Q [KTOT*DM];          // 336 x 1024
__device__ float g_bv[DS];
__device__ float g_bw[NTAP*DS];
__device__ float g_qb[NTAP*DM];
__device__ float g_pooled[NB*DM];
__device__ __nv_bfloat16 g_Xh[(size_t)NT*KPAD];   // 44MB
__device__ __nv_bfloat16 g_Xl[(size_t)NT*KPAD];   // 44MB
__device__ __nv_bfloat16 g_QhT[(size_t)DM*KPAD];  // [n][k]
__device__ __nv_bfloat16 g_QlT[(size_t)DM*KPAD];

// ---------------- asm helpers ----------------
__device__ __forceinline__ uint32_t smem_u32(const void* p) {
    uint32_t a;
    asm("{ .reg .u64 t; cvta.to.shared.u64 t, %1; cvt.u32.u64 %0, t; }" : "=r"(a) : "l"(p));
    return a;
}
__device__ __forceinline__ void cp16(uint32_t dst, const void* src) {
    asm volatile("cp.async.cg.shared.global [%0], [%1], 16;" :: "r"(dst), "l"(src));
}
__device__ __forceinline__ void cp_commit() {
    asm volatile("cp.async.commit_group;" ::: "memory");
}
__device__ __forceinline__ void cp_wait1() {
    asm volatile("cp.async.wait_group 1;" ::: "memory");
}
__device__ __forceinline__ void cp_wait0() {
    asm volatile("cp.async.wait_group 0;" ::: "memory");
}
__device__ __forceinline__ void ldm_x4(uint32_t* r, uint32_t addr) {
    asm volatile("ldmatrix.sync.aligned.m8n8.x4.shared.b16 {%0,%1,%2,%3}, [%4];"
                 : "=r"(r[0]), "=r"(r[1]), "=r"(r[2]), "=r"(r[3]) : "r"(addr));
}
__device__ __forceinline__ void mma16816(float* c, const uint32_t* a, uint32_t b0, uint32_t b1) {
    asm volatile("mma.sync.aligned.m16n8k16.row.col.f32.bf16.bf16.f32 "
                 "{%0,%1,%2,%3}, {%4,%5,%6,%7}, {%8,%9}, {%0,%1,%2,%3};"
                 : "+f"(c[0]), "+f"(c[1]), "+f"(c[2]), "+f"(c[3])
                 : "r"(a[0]), "r"(a[1]), "r"(a[2]), "r"(a[3]), "r"(b0), "r"(b1));
}

// ---------------- tiny helpers ----------------
__global__ void kt_zero_pooled() {
    int i = blockIdx.x * blockDim.x + threadIdx.x;
    if (i < NB*DM) g_pooled[i] = 0.0f;
}
__global__ void kt_transpose(float* __restrict__ dst, const float* __restrict__ src,
                             int R, int Cc) {
    int idx = blockIdx.x * blockDim.x + threadIdx.x;
    if (idx >= R*Cc) return;
    int r = idx / Cc, c = idx - r*Cc;
    dst[(size_t)c*R + r] = src[idx];
}
__global__ void kt_gemm32(float* __restrict__ Cc, const float* __restrict__ Aa,
                          const float* __restrict__ Bb, int M, int N, int K) {
    __shared__ float As[32][33];
    __shared__ float Bs[32][33];
    int tx = threadIdx.x & 15, ty = threadIdx.x >> 4;
    int n0 = blockIdx.x*32, m0 = blockIdx.y*32;
    float a00=0.f,a01=0.f,a10=0.f,a11=0.f;
    for (int k0 = 0; k0 < K; k0 += 32) {
#pragma unroll
        for (int j = 0; j < 4; j++) {
            int e = j*256 + threadIdx.x;
            int r = e >> 5, c = e & 31;
            As[r][c] = (m0+r < M && k0+c < K) ? Aa[(size_t)(m0+r)*K + k0+c] : 0.f;
            Bs[r][c] = (k0+r < K && n0+c < N) ? Bb[(size_t)(k0+r)*N + n0+c] : 0.f;
        }
        __syncthreads();
#pragma unroll
        for (int kk = 0; kk < 32; kk++) {
            float x0 = As[ty*2][kk],  x1 = As[ty*2+1][kk];
            float y0 = Bs[kk][tx*2],  y1 = Bs[kk][tx*2+1];
            a00 += x0*y0; a01 += x0*y1; a10 += x1*y0; a11 += x1*y1;
        }
        __syncthreads();
    }
    int m = m0 + ty*2, n = n0 + tx*2;
    if (m   < M && n   < N) Cc[(size_t)m*N + n]       = a00;
    if (m   < M && n+1 < N) Cc[(size_t)m*N + n+1]     = a01;
    if (m+1 < M && n   < N) Cc[(size_t)(m+1)*N + n]   = a10;
    if (m+1 < M && n+1 < N) Cc[(size_t)(m+1)*N + n+1] = a11;
}
__global__ void kt_bv(const float* __restrict__ Bm, const float* __restrict__ b_in) {
    int c = threadIdx.x;
    float s = 0.f;
    for (int k = 0; k < DM; k++) s += Bm[(size_t)c*DM + k] * b_in[k];
    g_bv[c] = s;
}
__global__ void kt_bias() {
    __shared__ float cur[DS];
    int c = threadIdx.x;
    float v = g_bv[c];
    cur[c] = v;
    float accum = v;
    g_bw[c] = v;
    for (int s = 1; s < NTAP; s++) {
        __syncthreads();
        float nxt = 0.f;
#pragma unroll 8
        for (int k = 0; k < DS; k++) nxt += cur[k] * g_G[k*DS + c];
        __syncthreads();
        cur[c] = nxt;
        accum += nxt;
        g_bw[s*DS + c] = accum;
    }
}

// ---------------- bf16 split prep ----------------
__global__ void kt_splitX(const float* __restrict__ x) {
    size_t e = (size_t)blockIdx.x * blockDim.x + threadIdx.x;
    if (e >= (size_t)NT*KPAD) return;
    int k = (int)(e % KPAD);
    int t = (int)(e / KPAD);
    float v = 0.f;
    if (k < KTOT) {
        int b = k / NIN, i = k - b*NIN;
        int tt = t - b;
        int bbase = t & ~(NL-1);
        if (tt >= bbase) v = x[(size_t)tt*NIN + i];
    }
    __nv_bfloat16 hi = __float2bfloat16(v);
    __nv_bfloat16 lo = __float2bfloat16(v - __bfloat162float(hi));
    g_Xh[e] = hi;
    g_Xl[e] = lo;
}
__global__ void kt_splitQT() {
    int e = blockIdx.x * blockDim.x + threadIdx.x;
    if (e >= DM*KPAD) return;
    int k = e % KPAD, n = e / KPAD;
    float v = (k < KTOT) ? g_Q[(size_t)k*DM + n] : 0.f;
    __nv_bfloat16 hi = __float2bfloat16(v);
    __nv_bfloat16 lo = __float2bfloat16(v - __bfloat162float(hi));
    g_QhT[e] = hi;
    g_QlT[e] = lo;
}

// ================= mma.sync bf16 GEMM: Yraw = Xtilde @ Q =================
// CTA 128x128 tile, 8 warps (4M x 2N), warp 32x64. K = 33 chunks of 32,
// pass p: (A,B) = (Xh,Qh),(Xl,Qh),(Xh,Ql). Double-buffered cp.async.
// smem row: 32 bf16 padded to 40 (80B) -> conflict-free ldmatrix.
#define ROWB 80
#define STGB (128*ROWB)
__global__ __launch_bounds__(256, 2) void kt_mma(float* __restrict__ out) {
    __shared__ __align__(16) char sA[2*STGB];
    __shared__ __align__(16) char sB[2*STGB];
    const int tid = threadIdx.x, lane = tid & 31, warp = tid >> 5;
    const int wm = warp >> 1, wn = warp & 1;
    const int t0 = (int)(blockIdx.x >> 3) * 128;
    const int n0 = (int)(blockIdx.x & 7) * 128;
    const uint32_t aBase = smem_u32(sA);
    const uint32_t bBase = smem_u32(sB);

    // cp.async stage issue for chunk c into buffer buf
    auto issue = [&](int c, int buf) {
        int pass = c / 11;
        int kb = (c - pass*11) * 32;
        const __nv_bfloat16* Ap = (pass == 1) ? g_Xl : g_Xh;
        const __nv_bfloat16* Bp = (pass == 2) ? g_QlT : g_QhT;
#pragma unroll
        for (int i = 0; i < 2; i++) {
            int e = i*256 + tid;            // 0..511
            int row = e >> 2, g = e & 3;    // 128 rows x 4 16B-groups
            cp16(aBase + buf*STGB + row*ROWB + g*16,
                 Ap + (size_t)(t0 + row)*KPAD + kb + g*8);
            cp16(bBase + buf*STGB + row*ROWB + g*16,
                 Bp + (size_t)(n0 + row)*KPAD + kb + g*8);
        }
        cp_commit();
    };

    float acc[2][8][4];
#pragma unroll
    for (int mt = 0; mt < 2; mt++)
#pragma unroll
        for (int nt = 0; nt < 8; nt++)
#pragma unroll
            for (int j = 0; j < 4; j++) acc[mt][nt][j] = 0.f;

    issue(0, 0);
    for (int c = 0; c < NCHUNK; c++) {
        int buf = c & 1;
        if (c + 1 < NCHUNK) { issue(c + 1, (c + 1) & 1); cp_wait1(); }
        else cp_wait0();
        __syncthreads();

#pragma unroll
        for (int k16 = 0; k16 < 32; k16 += 16) {
            // A fragments: 2 x ldmatrix.x4 (16x16 each)
            uint32_t afr[2][4];
#pragma unroll
            for (int mt = 0; mt < 2; mt++) {
                int row = wm*32 + mt*16 + (lane & 15);
                int kk = k16 + ((lane >> 4) << 3);
                ldm_x4(afr[mt], aBase + buf*STGB + row*ROWB + kk*2);
            }
            // B fragments: 4 x ldmatrix.x4, each covers 16 n x 16 k
            uint32_t bfr[4][4];
#pragma unroll
            for (int bt = 0; bt < 4; bt++) {
                int n = wn*64 + bt*16 + (lane & 7) + ((lane >> 4) << 3);
                int kk = k16 + (((lane >> 3) & 1) << 3);
                ldm_x4(bfr[bt], bBase + buf*STGB + n*ROWB + kk*2);
            }
#pragma unroll
            for (int mt = 0; mt < 2; mt++)
#pragma unroll
                for (int nt = 0; nt < 8; nt++) {
                    const uint32_t* bp = bfr[nt >> 1];
                    int o = (nt & 1) * 2;
                    mma16816(acc[mt][nt], afr[mt], bp[o], bp[o+1]);
                }
        }
        __syncthreads();
    }

    // epilogue: raw Y store (float2, m16n8 fragment layout)
    const int qr = lane >> 2, qc = (lane & 3) * 2;
#pragma unroll
    for (int mt = 0; mt < 2; mt++) {
#pragma unroll
        for (int nt = 0; nt < 8; nt++) {
            int row = t0 + wm*32 + mt*16 + qr;
            int col = n0 + wn*64 + nt*8 + qc;
            float2 v0 = make_float2(acc[mt][nt][0], acc[mt][nt][1]);
            float2 v1 = make_float2(acc[mt][nt][2], acc[mt][nt][3]);
            *(float2*)&out[(size_t)LOGITS_OFF + (size_t)row*DM + col]     = v0;
            *(float2*)&out[(size_t)LOGITS_OFF + (size_t)(row+8)*DM + col] = v1;
        }
    }
}

// ---------------- activation epilogue ----------------
__device__ __forceinline__ float gelu_exact(float y) {
    return 0.5f * y * (1.0f + erff(y * 0.70710678118654752f));
}
__device__ __forceinline__ float fixv(float v) {
    if (isnan(v)) return 0.f;
    if (isinf(v)) return v > 0.f ? 1000000.0f : -1000000.0f;
    return v;
}

// LN pass: qbias + GELU + LayerNorm + nan_to_num + pool. 64 rows per block.
__global__ __launch_bounds__(256) void kt_ln(const float* __restrict__ gamma,
                                             const float* __restrict__ beta,
                                             float* __restrict__ out) {
    __shared__ float w1[8], w2[8], s_mu, s_rs;
    const int tid = threadIdx.x, lane = tid & 31, wid = tid >> 5;
    const int t0 = blockIdx.x * 64;
    const float4 gg = *(const float4*)&gamma[tid*4];
    const float4 bb = *(const float4*)&beta[tid*4];
    float p0 = 0.f, p1 = 0.f, p2 = 0.f, p3 = 0.f;

    for (int r = 0; r < 64; r++) {
        int t = t0 + r;
        int l = t & (NL-1);
        int s = l < NTAP-1 ? l : NTAP-1;
        size_t o = (size_t)LOGITS_OFF + (size_t)t*DM + tid*4;
        float4 y = *(const float4*)&out[o];
        float4 q = *(const float4*)&g_qb[s*DM + tid*4];
        float v0 = gelu_exact(y.x + q.x);
        float v1 = gelu_exact(y.y + q.y);
        float v2 = gelu_exact(y.z + q.z);
        float v3 = gelu_exact(y.w + q.w);
        float s1 = v0 + v1 + v2 + v3;
        float s2 = v0*v0 + v1*v1 + v2*v2 + v3*v3;
#pragma unroll
        for (int off = 16; off > 0; off >>= 1) {
            s1 += __shfl_down_sync(0xffffffffu, s1, off);
            s2 += __shfl_down_sync(0xffffffffu, s2, off);
        }
        if (lane == 0) { w1[wid] = s1; w2[wid] = s2; }
        __syncthreads();
        if (tid == 0) {
            float a = 0.f, b2 = 0.f;
#pragma unroll
            for (int w = 0; w < 8; w++) { a += w1[w]; b2 += w2[w]; }
            float mu = a * (1.0f/DM);
            s_mu = mu;
            s_rs = rsqrtf(b2 * (1.0f/DM) - mu*mu + 1e-5f);
        }
        __syncthreads();
        float mu = s_mu, rs = s_rs;
        float4 nv;
        nv.x = fixv((v0 - mu)*rs*gg.x + bb.x);
        nv.y = fixv((v1 - mu)*rs*gg.y + bb.y);
        nv.z = fixv((v2 - mu)*rs*gg.z + bb.z);
        nv.w = fixv((v3 - mu)*rs*gg.w + bb.w);
        *(float4*)&out[o] = nv;
        p0 += nv.x; p1 += nv.y; p2 += nv.z; p3 += nv.w;
    }
    const float inv = 1.0f / (float)NL;
    float* pp = &g_pooled[(t0 >> 10)*DM + tid*4];
    atomicAdd(pp+0, p0*inv);
    atomicAdd(pp+1, p1*inv);
    atomicAdd(pp+2, p2*inv);
    atomicAdd(pp+3, p3*inv);
}

// ---------------- logits ----------------
__global__ void kt_logits(const float* __restrict__ W_fc, const float* __restrict__ b_fc,
                          float* __restrict__ out) {
    int b = blockIdx.x;
    int lane = threadIdx.x;
    for (int c = 0; c < NCL; c++) {
        float s = 0.f;
        for (int d = lane; d < DM; d += 32)
            s += g_pooled[b*DM + d] * W_fc[c*DM + d];
#pragma unroll
        for (int off = 16; off > 0; off >>= 1)
            s += __shfl_down_sync(0xffffffffu, s, off);
        if (lane == 0) out[b*NCL + c] = s + b_fc[c];
    }
}

// ---------------- launch ----------------
extern "C" void kernel_launch(void* const* d_in, const int* in_sizes, int n_in,
                              void* d_out, int out_size) {
    const float* x     = (const float*)d_in[0];
    const float* W_in  = (const float*)d_in[1];
    const float* b_in  = (const float*)d_in[2];
    const float* A     = (const float*)d_in[3];
    const float* Bm    = (const float*)d_in[4];
    const float* C     = (const float*)d_in[5];
    const float* gamma = (const float*)d_in[6];
    const float* beta  = (const float*)d_in[7];
    const float* W_fc  = (const float*)d_in[8];
    const float* b_fc  = (const float*)d_in[9];
    float* out = (float*)d_out;

    float *pG, *pG2, *pG4, *pM, *pR, *pCT, *pQ, *pBW, *pQB;
    cudaGetSymbolAddress((void**)&pG,  g_G);
    cudaGetSymbolAddress((void**)&pG2, g_G2);
    cudaGetSymbolAddress((void**)&pG4, g_G4);
    cudaGetSymbolAddress((void**)&pM,  g_M);
    cudaGetSymbolAddress((void**)&pR,  g_R);
    cudaGetSymbolAddress((void**)&pCT, g_CT);
    cudaGetSymbolAddress((void**)&pQ,  g_Q);
    cudaGetSymbolAddress((void**)&pBW, g_bw);
    cudaGetSymbolAddress((void**)&pQB, g_qb);

    // ---- precompute chain (tiny fp32 GEMMs) ----
    kt_transpose<<<DS*DS/256, 256>>>(pG, A, DS, DS);
    kt_transpose<<<DM*DS/256, 256>>>(pCT, C, DM, DS);
    kt_gemm32<<<dim3(1,8), 256>>>(pM, Bm, W_in, DS, NIN, DM);
    kt_transpose<<<DS*NIN/256 + 1, 256>>>(pR, pM, DS, NIN);
    kt_gemm32<<<dim3(8,8), 256>>>(pG2, pG, pG, DS, DS, DS);
    kt_gemm32<<<dim3(8,8), 256>>>(pG4, pG2, pG2, DS, DS, DS);
    kt_gemm32<<<dim3(8,1), 256>>>(pR + 1*NIN*DS, pR, pG,  NIN, DS, DS);
    kt_gemm32<<<dim3(8,1), 256>>>(pR + 2*NIN*DS, pR, pG2, NIN, DS, DS);
    kt_gemm32<<<dim3(8,1), 256>>>(pR + 3*NIN*DS, pR + 1*NIN*DS, pG2, NIN, DS, DS);
    kt_gemm32<<<dim3(8,4), 256>>>(pR + 4*NIN*DS, pR, pG4, 4*NIN, DS, DS);
    kt_gemm32<<<dim3(8,4), 256>>>(pR + 8*NIN*DS, pR + 4*NIN*DS, pG4, 4*NIN, DS, DS);
    kt_gemm32<<<dim3(32,11), 256>>>(pQ, pR, pCT, KTOT, DM, DS);
    kt_bv<<<1, DS>>>(Bm, b_in);
    kt_bias<<<1, DS>>>();
    kt_gemm32<<<dim3(32,1), 256>>>(pQB, pBW, pCT, NTAP, DM, DS);
    kt_zero_pooled<<<NB*DM/256, 256>>>();

    // ---- bf16 split prep ----
    kt_splitX<<<(int)(((size_t)NT*KPAD + 255)/256), 256>>>(x);
    kt_splitQT<<<(DM*KPAD + 255)/256, 256>>>();

    // ---- tensor-core GEMM (mma.sync) + LN + logits ----
    kt_mma<<<(NT/128)*8, 256>>>(out);
    kt_ln<<<NT/64, 256>>>(gamma, beta, out);
    kt_logits<<<NB, 32>>>(W_fc, b_fc, out);
}

// round 6
// speedup vs baseline: 2.0773x; 1.2254x over previous
#include <cuda_runtime.h>
#include <cuda_bf16.h>
#include <math.h>
#include <stdint.h>

// ---------------- problem constants ----------------
#define NB   64
#define NL   1024
#define NT   65536        // NB*NL tokens
#define DM   1024
#define DS   256
#define NIN  28
#define NCL  10
#define NTAP 8
#define KTOT (NTAP*NIN)   // 224
#define KPAD 224          // 7 chunks of 32, no padding needed
#define CHPP 7            // chunks per pass
#define NCHUNK (3*CHPP)   // 21
#define LOGITS_OFF 640    // NB*NCL floats, activations follow

// ---------------- device scratch ----------------
__device__ float g_G [DS*DS];
__device__ float g_G2[DS*DS];
__device__ float g_G4[DS*DS];
__device__ float g_M [DS*NIN];
__device__ float g_R [NTAP*NIN*DS];      // 224 x 256
__device__ float g_CT[DS*DM];
__device__ float g_Q [KTOT*DM];          // 224 x 1024
__device__ float g_bv[DS];
__device__ float g_bw[NTAP*DS];
__device__ float g_qb[NTAP*DM];
__device__ float g_pooled[NB*DM];
__device__ __nv_bfloat16 g_Xh[(size_t)NT*KPAD];   // 28MB
__device__ __nv_bfloat16 g_Xl[(size_t)NT*KPAD];   // 28MB
__device__ __nv_bfloat16 g_QhT[(size_t)DM*KPAD];  // [n][k]
__device__ __nv_bfloat16 g_QlT[(size_t)DM*KPAD];

// ---------------- asm helpers ----------------
__device__ __forceinline__ uint32_t smem_u32(const void* p) {
    uint32_t a;
    asm("{ .reg .u64 t; cvta.to.shared.u64 t, %1; cvt.u32.u64 %0, t; }" : "=r"(a) : "l"(p));
    return a;
}
__device__ __forceinline__ void cp16(uint32_t dst, const void* src) {
    asm volatile("cp.async.cg.shared.global [%0], [%1], 16;" :: "r"(dst), "l"(src));
}
__device__ __forceinline__ void cp_commit() {
    asm volatile("cp.async.commit_group;" ::: "memory");
}
__device__ __forceinline__ void cp_wait1() {
    asm volatile("cp.async.wait_group 1;" ::: "memory");
}
__device__ __forceinline__ void cp_wait0() {
    asm volatile("cp.async.wait_group 0;" ::: "memory");
}
__device__ __forceinline__ void ldm_x4(uint32_t* r, uint32_t addr) {
    asm volatile("ldmatrix.sync.aligned.m8n8.x4.shared.b16 {%0,%1,%2,%3}, [%4];"
                 : "=r"(r[0]), "=r"(r[1]), "=r"(r[2]), "=r"(r[3]) : "r"(addr));
}
__device__ __forceinline__ void mma16816(float* c, const uint32_t* a, uint32_t b0, uint32_t b1) {
    asm volatile("mma.sync.aligned.m16n8k16.row.col.f32.bf16.bf16.f32 "
                 "{%0,%1,%2,%3}, {%4,%5,%6,%7}, {%8,%9}, {%0,%1,%2,%3};"
                 : "+f"(c[0]), "+f"(c[1]), "+f"(c[2]), "+f"(c[3])
                 : "r"(a[0]), "r"(a[1]), "r"(a[2]), "r"(a[3]), "r"(b0), "r"(b1));
}

// ---------------- tiny helpers ----------------
__global__ void kt_zero_pooled() {
    int i = blockIdx.x * blockDim.x + threadIdx.x;
    if (i < NB*DM) g_pooled[i] = 0.0f;
}
__global__ void kt_transpose(float* __restrict__ dst, const float* __restrict__ src,
                             int R, int Cc) {
    int idx = blockIdx.x * blockDim.x + threadIdx.x;
    if (idx >= R*Cc) return;
    int r = idx / Cc, c = idx - r*Cc;
    dst[(size_t)c*R + r] = src[idx];
}
__global__ void kt_gemm32(float* __restrict__ Cc, const float* __restrict__ Aa,
                          const float* __restrict__ Bb, int M, int N, int K) {
    __shared__ float As[32][33];
    __shared__ float Bs[32][33];
    int tx = threadIdx.x & 15, ty = threadIdx.x >> 4;
    int n0 = blockIdx.x*32, m0 = blockIdx.y*32;
    float a00=0.f,a01=0.f,a10=0.f,a11=0.f;
    for (int k0 = 0; k0 < K; k0 += 32) {
#pragma unroll
        for (int j = 0; j < 4; j++) {
            int e = j*256 + threadIdx.x;
            int r = e >> 5, c = e & 31;
            As[r][c] = (m0+r < M && k0+c < K) ? Aa[(size_t)(m0+r)*K + k0+c] : 0.f;
            Bs[r][c] = (k0+r < K && n0+c < N) ? Bb[(size_t)(k0+r)*N + n0+c] : 0.f;
        }
        __syncthreads();
#pragma unroll
        for (int kk = 0; kk < 32; kk++) {
            float x0 = As[ty*2][kk],  x1 = As[ty*2+1][kk];
            float y0 = Bs[kk][tx*2],  y1 = Bs[kk][tx*2+1];
            a00 += x0*y0; a01 += x0*y1; a10 += x1*y0; a11 += x1*y1;
        }
        __syncthreads();
    }
    int m = m0 + ty*2, n = n0 + tx*2;
    if (m   < M && n   < N) Cc[(size_t)m*N + n]       = a00;
    if (m   < M && n+1 < N) Cc[(size_t)m*N + n+1]     = a01;
    if (m+1 < M && n   < N) Cc[(size_t)(m+1)*N + n]   = a10;
    if (m+1 < M && n+1 < N) Cc[(size_t)(m+1)*N + n+1] = a11;
}
__global__ void kt_bv(const float* __restrict__ Bm, const float* __restrict__ b_in) {
    int c = threadIdx.x;
    float s = 0.f;
    for (int k = 0; k < DM; k++) s += Bm[(size_t)c*DM + k] * b_in[k];
    g_bv[c] = s;
}
__global__ void kt_bias() {
    __shared__ float cur[DS];
    int c = threadIdx.x;
    float v = g_bv[c];
    cur[c] = v;
    float accum = v;
    g_bw[c] = v;
    for (int s = 1; s < NTAP; s++) {
        __syncthreads();
        float nxt = 0.f;
#pragma unroll 8
        for (int k = 0; k < DS; k++) nxt += cur[k] * g_G[k*DS + c];
        __syncthreads();
        cur[c] = nxt;
        accum += nxt;
        g_bw[s*DS + c] = accum;
    }
}

// ---------------- bf16 split prep ----------------
__global__ void kt_splitX(const float* __restrict__ x) {
    size_t e = (size_t)blockIdx.x * blockDim.x + threadIdx.x;
    if (e >= (size_t)NT*KPAD) return;
    int k = (int)(e % KPAD);
    int t = (int)(e / KPAD);
    int b = k / NIN, i = k - b*NIN;
    int tt = t - b;
    int bbase = t & ~(NL-1);
    float v = (tt >= bbase) ? x[(size_t)tt*NIN + i] : 0.f;
    __nv_bfloat16 hi = __float2bfloat16(v);
    __nv_bfloat16 lo = __float2bfloat16(v - __bfloat162float(hi));
    g_Xh[e] = hi;
    g_Xl[e] = lo;
}
__global__ void kt_splitQT() {
    int e = blockIdx.x * blockDim.x + threadIdx.x;
    if (e >= DM*KPAD) return;
    int k = e % KPAD, n = e / KPAD;
    float v = g_Q[(size_t)k*DM + n];
    __nv_bfloat16 hi = __float2bfloat16(v);
    __nv_bfloat16 lo = __float2bfloat16(v - __bfloat162float(hi));
    g_QhT[e] = hi;
    g_QlT[e] = lo;
}

// ================= mma.sync bf16 GEMM: Yraw = Xtilde @ Q =================
// CTA 128x128 tile, 8 warps (4M x 2N), warp 32x64. K = 21 chunks of 32,
// pass p: (A,B) = (Xh,Qh),(Xl,Qh),(Xh,Ql). Double-buffered cp.async.
// smem row: 32 bf16 padded to 40 (80B) -> conflict-free ldmatrix.
#define ROWB 80
#define STGB (128*ROWB)
#define EROW 136          // epilogue staging row stride (floats)
__global__ __launch_bounds__(256, 2) void kt_mma(float* __restrict__ out) {
    __shared__ __align__(16) char smem[4*STGB];   // 40KB: A2bufs + B2bufs / epilogue
    char* sA = smem;
    char* sB = smem + 2*STGB;
    const int tid = threadIdx.x, lane = tid & 31, warp = tid >> 5;
    const int wm = warp >> 1, wn = warp & 1;
    const int t0 = (int)(blockIdx.x >> 3) * 128;
    const int n0 = (int)(blockIdx.x & 7) * 128;
    const uint32_t aBase = smem_u32(sA);
    const uint32_t bBase = smem_u32(sB);

    auto issue = [&](int c, int buf) {
        int pass = c / CHPP;
        int kb = (c - pass*CHPP) * 32;
        const __nv_bfloat16* Ap = (pass == 1) ? g_Xl : g_Xh;
        const __nv_bfloat16* Bp = (pass == 2) ? g_QlT : g_QhT;
#pragma unroll
        for (int i = 0; i < 2; i++) {
            int e = i*256 + tid;            // 0..511
            int row = e >> 2, g = e & 3;    // 128 rows x 4 16B-groups
            cp16(aBase + buf*STGB + row*ROWB + g*16,
                 Ap + (size_t)(t0 + row)*KPAD + kb + g*8);
            cp16(bBase + buf*STGB + row*ROWB + g*16,
                 Bp + (size_t)(n0 + row)*KPAD + kb + g*8);
        }
        cp_commit();
    };

    float acc[2][8][4];
#pragma unroll
    for (int mt = 0; mt < 2; mt++)
#pragma unroll
        for (int nt = 0; nt < 8; nt++)
#pragma unroll
            for (int j = 0; j < 4; j++) acc[mt][nt][j] = 0.f;

    issue(0, 0);
    for (int c = 0; c < NCHUNK; c++) {
        int buf = c & 1;
        if (c + 1 < NCHUNK) { issue(c + 1, (c + 1) & 1); cp_wait1(); }
        else cp_wait0();
        __syncthreads();

#pragma unroll
        for (int k16 = 0; k16 < 32; k16 += 16) {
            uint32_t afr[2][4];
#pragma unroll
            for (int mt = 0; mt < 2; mt++) {
                int row = wm*32 + mt*16 + (lane & 15);
                int kk = k16 + ((lane >> 4) << 3);
                ldm_x4(afr[mt], aBase + buf*STGB + row*ROWB + kk*2);
            }
            uint32_t bfr[4][4];
#pragma unroll
            for (int bt = 0; bt < 4; bt++) {
                int n = wn*64 + bt*16 + (lane & 7) + ((lane >> 4) << 3);
                int kk = k16 + (((lane >> 3) & 1) << 3);
                ldm_x4(bfr[bt], bBase + buf*STGB + n*ROWB + kk*2);
            }
#pragma unroll
            for (int mt = 0; mt < 2; mt++)
#pragma unroll
                for (int nt = 0; nt < 8; nt++) {
                    const uint32_t* bp = bfr[nt >> 1];
                    int o = (nt & 1) * 2;
                    mma16816(acc[mt][nt], afr[mt], bp[o], bp[o+1]);
                }
        }
        __syncthreads();
    }

    // ---- epilogue: smem-staged coalesced float4 stores (two 64-row halves) ----
    float* Ysh = (float*)smem;    // 64 x EROW floats = 34.8KB
    const int qr = lane >> 2, qc = (lane & 3) * 2;
#pragma unroll
    for (int h = 0; h < 2; h++) {
        __syncthreads();
        if ((wm >> 1) == h) {
            int rbase = (wm & 1) * 32;
#pragma unroll
            for (int mt = 0; mt < 2; mt++)
#pragma unroll
                for (int nt = 0; nt < 8; nt++) {
                    int row = rbase + mt*16 + qr;
                    int col = wn*64 + nt*8 + qc;
                    *(float2*)&Ysh[row*EROW + col]     = make_float2(acc[mt][nt][0], acc[mt][nt][1]);
                    *(float2*)&Ysh[(row+8)*EROW + col] = make_float2(acc[mt][nt][2], acc[mt][nt][3]);
                }
        }
        __syncthreads();
#pragma unroll
        for (int i = 0; i < 8; i++) {
            int e = i*256 + tid;
            int row = e >> 5, c4 = e & 31;
            float4 v = *(const float4*)&Ysh[row*EROW + c4*4];
            *(float4*)&out[(size_t)LOGITS_OFF + (size_t)(t0 + h*64 + row)*DM + n0 + c4*4] = v;
        }
    }
}

// ---------------- activation epilogue ----------------
__device__ __forceinline__ float gelu_exact(float y) {
    return 0.5f * y * (1.0f + erff(y * 0.70710678118654752f));
}
__device__ __forceinline__ float fixv(float v) {
    if (isnan(v)) return 0.f;
    if (isinf(v)) return v > 0.f ? 1000000.0f : -1000000.0f;
    return v;
}

// LN pass: warp-per-16-rows, no block syncs. qbias + GELU + LN + nan_to_num + pool.
// grid 512, block 256 (8 warps): warp w of block g handles rows (g*8+w)*16 .. +15.
__global__ __launch_bounds__(256) void kt_ln(const float* __restrict__ gamma,
                                             const float* __restrict__ beta,
                                             float* __restrict__ out) {
    const int tid = threadIdx.x, lane = tid & 31, wid = tid >> 5;
    const int wg = blockIdx.x * 8 + wid;
    const int t0 = wg * 16;                 // 16 rows, same batch (1024 % 16 == 0)
    float pool[8][4];
#pragma unroll
    for (int j = 0; j < 8; j++)
#pragma unroll
        for (int q = 0; q < 4; q++) pool[j][q] = 0.f;

    for (int r = 0; r < 16; r++) {
        int t = t0 + r;
        int l = t & (NL-1);
        int s = l < NTAP-1 ? l : NTAP-1;
        size_t o = (size_t)LOGITS_OFF + (size_t)t*DM + lane*4;
        float4 v[8];
        float s1 = 0.f, s2 = 0.f;
#pragma unroll
        for (int j = 0; j < 8; j++) {
            float4 y = *(const float4*)&out[o + j*128];
            float4 q = *(const float4*)&g_qb[s*DM + j*128 + lane*4];
            v[j].x = gelu_exact(y.x + q.x);
            v[j].y = gelu_exact(y.y + q.y);
            v[j].z = gelu_exact(y.z + q.z);
            v[j].w = gelu_exact(y.w + q.w);
            s1 += v[j].x + v[j].y + v[j].z + v[j].w;
            s2 += v[j].x*v[j].x + v[j].y*v[j].y + v[j].z*v[j].z + v[j].w*v[j].w;
        }
#pragma unroll
        for (int off = 16; off > 0; off >>= 1) {
            s1 += __shfl_xor_sync(0xffffffffu, s1, off);
            s2 += __shfl_xor_sync(0xffffffffu, s2, off);
        }
        float mu = s1 * (1.0f/DM);
        float rs = rsqrtf(s2 * (1.0f/DM) - mu*mu + 1e-5f);
#pragma unroll
        for (int j = 0; j < 8; j++) {
            float4 g = *(const float4*)&gamma[j*128 + lane*4];
            float4 b = *(const float4*)&beta[j*128 + lane*4];
            float4 nv;
            nv.x = fixv((v[j].x - mu)*rs*g.x + b.x);
            nv.y = fixv((v[j].y - mu)*rs*g.y + b.y);
            nv.z = fixv((v[j].z - mu)*rs*g.z + b.z);
            nv.w = fixv((v[j].w - mu)*rs*g.w + b.w);
            *(float4*)&out[o + j*128] = nv;
            pool[j][0] += nv.x; pool[j][1] += nv.y; pool[j][2] += nv.z; pool[j][3] += nv.w;
        }
    }
    const float inv = 1.0f / (float)NL;
    const int b = t0 >> 10;
#pragma unroll
    for (int j = 0; j < 8; j++) {
        float* pp = &g_pooled[b*DM + j*128 + lane*4];
        atomicAdd(pp+0, pool[j][0]*inv);
        atomicAdd(pp+1, pool[j][1]*inv);
        atomicAdd(pp+2, pool[j][2]*inv);
        atomicAdd(pp+3, pool[j][3]*inv);
    }
}

// ---------------- logits ----------------
__global__ void kt_logits(const float* __restrict__ W_fc, const float* __restrict__ b_fc,
                          float* __restrict__ out) {
    int b = blockIdx.x;
    int lane = threadIdx.x;
    for (int c = 0; c < NCL; c++) {
        float s = 0.f;
        for (int d = lane; d < DM; d += 32)
            s += g_pooled[b*DM + d] * W_fc[c*DM + d];
#pragma unroll
        for (int off = 16; off > 0; off >>= 1)
            s += __shfl_down_sync(0xffffffffu, s, off);
        if (lane == 0) out[b*NCL + c] = s + b_fc[c];
    }
}

// ---------------- launch ----------------
extern "C" void kernel_launch(void* const* d_in, const int* in_sizes, int n_in,
                              void* d_out, int out_size) {
    const float* x     = (const float*)d_in[0];
    const float* W_in  = (const float*)d_in[1];
    const float* b_in  = (const float*)d_in[2];
    const float* A     = (const float*)d_in[3];
    const float* Bm    = (const float*)d_in[4];
    const float* C     = (const float*)d_in[5];
    const float* gamma = (const float*)d_in[6];
    const float* beta  = (const float*)d_in[7];
    const float* W_fc  = (const float*)d_in[8];
    const float* b_fc  = (const float*)d_in[9];
    float* out = (float*)d_out;

    float *pG, *pG2, *pG4, *pM, *pR, *pCT, *pQ, *pBW, *pQB;
    cudaGetSymbolAddress((void**)&pG,  g_G);
    cudaGetSymbolAddress((void**)&pG2, g_G2);
    cudaGetSymbolAddress((void**)&pG4, g_G4);
    cudaGetSymbolAddress((void**)&pM,  g_M);
    cudaGetSymbolAddress((void**)&pR,  g_R);
    cudaGetSymbolAddress((void**)&pCT, g_CT);
    cudaGetSymbolAddress((void**)&pQ,  g_Q);
    cudaGetSymbolAddress((void**)&pBW, g_bw);
    cudaGetSymbolAddress((void**)&pQB, g_qb);

    // ---- precompute chain (tiny fp32 GEMMs) ----
    kt_transpose<<<DS*DS/256, 256>>>(pG, A, DS, DS);
    kt_transpose<<<DM*DS/256, 256>>>(pCT, C, DM, DS);
    kt_gemm32<<<dim3(1,8), 256>>>(pM, Bm, W_in, DS, NIN, DM);
    kt_transpose<<<DS*NIN/256 + 1, 256>>>(pR, pM, DS, NIN);
    kt_gemm32<<<dim3(8,8), 256>>>(pG2, pG, pG, DS, DS, DS);
    kt_gemm32<<<dim3(8,8), 256>>>(pG4, pG2, pG2, DS, DS, DS);
    kt_gemm32<<<dim3(8,1), 256>>>(pR + 1*NIN*DS, pR, pG,  NIN, DS, DS);
    kt_gemm32<<<dim3(8,1), 256>>>(pR + 2*NIN*DS, pR, pG2, NIN, DS, DS);
    kt_gemm32<<<dim3(8,1), 256>>>(pR + 3*NIN*DS, pR + 1*NIN*DS, pG2, NIN, DS, DS);
    kt_gemm32<<<dim3(8,4), 256>>>(pR + 4*NIN*DS, pR, pG4, 4*NIN, DS, DS);
    kt_gemm32<<<dim3(32,7), 256>>>(pQ, pR, pCT, KTOT, DM, DS);
    kt_bv<<<1, DS>>>(Bm, b_in);
    kt_bias<<<1, DS>>>();
    kt_gemm32<<<dim3(32,1), 256>>>(pQB, pBW, pCT, NTAP, DM, DS);
    kt_zero_pooled<<<NB*DM/256, 256>>>();

    // ---- bf16 split prep ----
    kt_splitX<<<(int)(((size_t)NT*KPAD + 255)/256), 256>>>(x);
    kt_splitQT<<<(DM*KPAD + 255)/256, 256>>>();

    // ---- tensor-core GEMM (mma.sync) + LN + logits ----
    kt_mma<<<(NT/128)*8, 256>>>(out);
    kt_ln<<<NT/128, 256>>>(gamma, beta, out);
    kt_logits<<<NB, 32>>>(W_fc, b_fc, out);
}

// round 7
// speedup vs baseline: 2.1479x; 1.0340x over previous
#include <cuda_runtime.h>
#include <cuda_bf16.h>
#include <math.h>
#include <stdint.h>

// ---------------- problem constants ----------------
#define NB   64
#define NL   1024
#define NT   65536        // NB*NL tokens
#define DM   1024
#define DS   256
#define NIN  28
#define NCL  10
#define NTAP 8
#define KTOT (NTAP*NIN)   // 224
#define KPAD 224          // 7 chunks of 32
#define NCHUNK 7
#define LOGITS_OFF 640    // NB*NCL floats, activations follow

// ---------------- device scratch ----------------
__device__ float g_G [DS*DS];
__device__ float g_G2[DS*DS];
__device__ float g_G4[DS*DS];
__device__ float g_M [DS*NIN];
__device__ float g_R [NTAP*NIN*DS];      // 224 x 256
__device__ float g_CT[DS*DM];
__device__ float g_Q [KTOT*DM];          // 224 x 1024
__device__ float g_bv[DS];
__device__ float g_bw[NTAP*DS];
__device__ float g_qb[NTAP*DM];
__device__ float g_pooled[NB*DM];
__device__ __nv_bfloat16 g_Xh[(size_t)NT*KPAD];   // 28MB
__device__ __nv_bfloat16 g_Xl[(size_t)NT*KPAD];   // 28MB
__device__ __nv_bfloat16 g_QhT[(size_t)DM*KPAD];  // [n][k]
__device__ __nv_bfloat16 g_QlT[(size_t)DM*KPAD];

// ---------------- asm helpers ----------------
__device__ __forceinline__ uint32_t smem_u32(const void* p) {
    uint32_t a;
    asm("{ .reg .u64 t; cvta.to.shared.u64 t, %1; cvt.u32.u64 %0, t; }" : "=r"(a) : "l"(p));
    return a;
}
__device__ __forceinline__ void cp16(uint32_t dst, const void* src) {
    asm volatile("cp.async.cg.shared.global [%0], [%1], 16;" :: "r"(dst), "l"(src));
}
__device__ __forceinline__ void cp_commit() {
    asm volatile("cp.async.commit_group;" ::: "memory");
}
__device__ __forceinline__ void cp_wait1() {
    asm volatile("cp.async.wait_group 1;" ::: "memory");
}
__device__ __forceinline__ void cp_wait0() {
    asm volatile("cp.async.wait_group 0;" ::: "memory");
}
__device__ __forceinline__ void ldm_x4(uint32_t* r, uint32_t addr) {
    asm volatile("ldmatrix.sync.aligned.m8n8.x4.shared.b16 {%0,%1,%2,%3}, [%4];"
                 : "=r"(r[0]), "=r"(r[1]), "=r"(r[2]), "=r"(r[3]) : "r"(addr));
}
__device__ __forceinline__ void mma16816(float* c, const uint32_t* a, uint32_t b0, uint32_t b1) {
    asm volatile("mma.sync.aligned.m16n8k16.row.col.f32.bf16.bf16.f32 "
                 "{%0,%1,%2,%3}, {%4,%5,%6,%7}, {%8,%9}, {%0,%1,%2,%3};"
                 : "+f"(c[0]), "+f"(c[1]), "+f"(c[2]), "+f"(c[3])
                 : "r"(a[0]), "r"(a[1]), "r"(a[2]), "r"(a[3]), "r"(b0), "r"(b1));
}

// ---------------- fused small prep: transposes + zero ----------------
// blocks [0,256): G = A^T ; [256, 1280): CT = C^T ; [1280, 1536): zero pooled
__global__ void kt_prep(const float* __restrict__ A, const float* __restrict__ C) {
    int b = blockIdx.x;
    int tid = threadIdx.x;
    if (b < 256) {
        int idx = b*256 + tid;
        int r = idx >> 8, c = idx & 255;
        g_G[c*DS + r] = A[idx];
    } else if (b < 1280) {
        int idx = (b - 256)*256 + tid;   // over DM*DS
        int r = idx >> 8, c = idx & 255; // C is (DM x DS)
        g_CT[c*DM + r] = C[idx];
    } else {
        int i = (b - 1280)*256 + tid;
        g_pooled[i] = 0.0f;
    }
}

__global__ void kt_gemm32(float* __restrict__ Cc, const float* __restrict__ Aa,
                          const float* __restrict__ Bb, int M, int N, int K) {
    __shared__ float As[32][33];
    __shared__ float Bs[32][33];
    int tx = threadIdx.x & 15, ty = threadIdx.x >> 4;
    int n0 = blockIdx.x*32, m0 = blockIdx.y*32;
    float a00=0.f,a01=0.f,a10=0.f,a11=0.f;
    for (int k0 = 0; k0 < K; k0 += 32) {
#pragma unroll
        for (int j = 0; j < 4; j++) {
            int e = j*256 + threadIdx.x;
            int r = e >> 5, c = e & 31;
            As[r][c] = (m0+r < M && k0+c < K) ? Aa[(size_t)(m0+r)*K + k0+c] : 0.f;
            Bs[r][c] = (k0+r < K && n0+c < N) ? Bb[(size_t)(k0+r)*N + n0+c] : 0.f;
        }
        __syncthreads();
#pragma unroll
        for (int kk = 0; kk < 32; kk++) {
            float x0 = As[ty*2][kk],  x1 = As[ty*2+1][kk];
            float y0 = Bs[kk][tx*2],  y1 = Bs[kk][tx*2+1];
            a00 += x0*y0; a01 += x0*y1; a10 += x1*y0; a11 += x1*y1;
        }
        __syncthreads();
    }
    int m = m0 + ty*2, n = n0 + tx*2;
    if (m   < M && n   < N) Cc[(size_t)m*N + n]       = a00;
    if (m   < M && n+1 < N) Cc[(size_t)m*N + n+1]     = a01;
    if (m+1 < M && n   < N) Cc[(size_t)(m+1)*N + n]   = a10;
    if (m+1 < M && n+1 < N) Cc[(size_t)(m+1)*N + n+1] = a11;
}

// bv = Bm @ b_in then bw chain (single block)
__global__ void kt_bvbias(const float* __restrict__ Bm, const float* __restrict__ b_in) {
    __shared__ float cur[DS];
    int c = threadIdx.x;
    float v = 0.f;
    for (int k = 0; k < DM; k++) v += Bm[(size_t)c*DM + k] * b_in[k];
    g_bv[c] = v;
    cur[c] = v;
    float accum = v;
    g_bw[c] = v;
    for (int s = 1; s < NTAP; s++) {
        __syncthreads();
        float nxt = 0.f;
#pragma unroll 8
        for (int k = 0; k < DS; k++) nxt += cur[k] * g_G[k*DS + c];
        __syncthreads();
        cur[c] = nxt;
        accum += nxt;
        g_bw[s*DS + c] = accum;
    }
}

__global__ void kt_transpose(float* __restrict__ dst, const float* __restrict__ src,
                             int R, int Cc) {
    int idx = blockIdx.x * blockDim.x + threadIdx.x;
    if (idx >= R*Cc) return;
    int r = idx / Cc, c = idx - r*Cc;
    dst[(size_t)c*R + r] = src[idx];
}

// ---------------- bf16 split prep ----------------
__global__ void kt_splitX(const float* __restrict__ x) {
    size_t e = (size_t)blockIdx.x * blockDim.x + threadIdx.x;
    if (e >= (size_t)NT*KPAD) return;
    int k = (int)(e % KPAD);
    int t = (int)(e / KPAD);
    int b = k / NIN, i = k - b*NIN;
    int tt = t - b;
    int bbase = t & ~(NL-1);
    float v = (tt >= bbase) ? x[(size_t)tt*NIN + i] : 0.f;
    __nv_bfloat16 hi = __float2bfloat16(v);
    __nv_bfloat16 lo = __float2bfloat16(v - __bfloat162float(hi));
    g_Xh[e] = hi;
    g_Xl[e] = lo;
}
__global__ void kt_splitQT() {
    int e = blockIdx.x * blockDim.x + threadIdx.x;
    if (e >= DM*KPAD) return;
    int k = e % KPAD, n = e / KPAD;
    float v = g_Q[(size_t)k*DM + n];
    __nv_bfloat16 hi = __float2bfloat16(v);
    __nv_bfloat16 lo = __float2bfloat16(v - __bfloat162float(hi));
    g_QhT[e] = hi;
    g_QlT[e] = lo;
}

// ================= fused-split mma.sync GEMM: Yraw = Xtilde @ Q =================
// CTA 128x256, 512 threads (16 warps, 4M x 4N, warp 32x64). 7 chunks of k=32.
// Per chunk: stage Ah,Al,Bh,Bl; accumulate AhBh + AlBh + AhBl into one acc.
#define ROWB 80
#define A_STG (128*ROWB)       // 10240
#define B_STG (256*ROWB)       // 20480
#define OFF_AH 0
#define OFF_AL (2*A_STG)       // 20480
#define OFF_BH (4*A_STG)       // 40960
#define OFF_BL (OFF_BH + 2*B_STG)  // 81920
#define SMEM_MMA 122880
#define EROW 264
__global__ __launch_bounds__(512, 1) void kt_mma(float* __restrict__ out) {
    extern __shared__ __align__(16) char smem[];
    const int tid = threadIdx.x, lane = tid & 31, warp = tid >> 5;
    const int wm = warp >> 2, wn = warp & 3;
    const int t0 = (int)(blockIdx.x >> 2) * 128;
    const int n0 = (int)(blockIdx.x & 3) * 256;
    const uint32_t base = smem_u32(smem);

    auto issue = [&](int c, int buf) {
        int kb = c * 32;
#pragma unroll
        for (int i = 0; i < 2; i++) {       // A: 1024 cp16 (2 variants x 128 rows x 4)
            int e = i*512 + tid;
            int var = e >> 9, row = (e >> 2) & 127, g = e & 3;
            const __nv_bfloat16* Ap = var ? g_Xl : g_Xh;
            uint32_t off = (var ? OFF_AL : OFF_AH) + buf*A_STG + row*ROWB + g*16;
            cp16(base + off, Ap + (size_t)(t0 + row)*KPAD + kb + g*8);
        }
#pragma unroll
        for (int i = 0; i < 4; i++) {       // B: 2048 cp16 (2 variants x 256 rows x 4)
            int e = i*512 + tid;
            int var = e >> 10, row = (e >> 2) & 255, g = e & 3;
            const __nv_bfloat16* Bp = var ? g_QlT : g_QhT;
            uint32_t off = (var ? OFF_BL : OFF_BH) + buf*B_STG + row*ROWB + g*16;
            cp16(base + off, Bp + (size_t)(n0 + row)*KPAD + kb + g*8);
        }
        cp_commit();
    };

    float acc[2][8][4];
#pragma unroll
    for (int mt = 0; mt < 2; mt++)
#pragma unroll
        for (int nt = 0; nt < 8; nt++)
#pragma unroll
            for (int j = 0; j < 4; j++) acc[mt][nt][j] = 0.f;

    issue(0, 0);
    for (int c = 0; c < NCHUNK; c++) {
        int buf = c & 1;
        if (c + 1 < NCHUNK) { issue(c + 1, (c + 1) & 1); cp_wait1(); }
        else cp_wait0();
        __syncthreads();

#pragma unroll
        for (int k16 = 0; k16 < 32; k16 += 16) {
            // A fragments, both variants
            uint32_t afr[2][2][4];
            {
                int kk = k16 + ((lane >> 4) << 3);
#pragma unroll
                for (int v = 0; v < 2; v++)
#pragma unroll
                    for (int mt = 0; mt < 2; mt++) {
                        int row = wm*32 + mt*16 + (lane & 15);
                        ldm_x4(afr[v][mt],
                               base + (v ? OFF_AL : OFF_AH) + buf*A_STG + row*ROWB + kk*2);
                    }
            }
            // B variant h: AhBh + AlBh
            {
                int n = wn*64 + (lane & 7) + ((lane >> 4) << 3);
                int kk = k16 + (((lane >> 3) & 1) << 3);
                uint32_t bfr[4][4];
#pragma unroll
                for (int bt = 0; bt < 4; bt++)
                    ldm_x4(bfr[bt], base + OFF_BH + buf*B_STG + (n + bt*16)*ROWB + kk*2);
#pragma unroll
                for (int mt = 0; mt < 2; mt++)
#pragma unroll
                    for (int nt = 0; nt < 8; nt++) {
                        const uint32_t* bp = bfr[nt >> 1];
                        int o = (nt & 1) * 2;
                        mma16816(acc[mt][nt], afr[0][mt], bp[o], bp[o+1]);
                        mma16816(acc[mt][nt], afr[1][mt], bp[o], bp[o+1]);
                    }
            }
            // B variant l: AhBl
            {
                int n = wn*64 + (lane & 7) + ((lane >> 4) << 3);
                int kk = k16 + (((lane >> 3) & 1) << 3);
                uint32_t bfr[4][4];
#pragma unroll
                for (int bt = 0; bt < 4; bt++)
                    ldm_x4(bfr[bt], base + OFF_BL + buf*B_STG + (n + bt*16)*ROWB + kk*2);
#pragma unroll
                for (int mt = 0; mt < 2; mt++)
#pragma unroll
                    for (int nt = 0; nt < 8; nt++) {
                        const uint32_t* bp = bfr[nt >> 1];
                        int o = (nt & 1) * 2;
                        mma16816(acc[mt][nt], afr[0][mt], bp[o], bp[o+1]);
                    }
            }
        }
        __syncthreads();
    }

    // ---- epilogue: two 64-row halves staged in smem, coalesced float4 stores ----
    float* Ysh = (float*)smem;    // 64 x EROW floats = 67.6KB
    const int qr = lane >> 2, qc = (lane & 3) * 2;
#pragma unroll
    for (int h = 0; h < 2; h++) {
        __syncthreads();
        if ((wm >> 1) == h) {
            int rbase = (wm & 1) * 32;
#pragma unroll
            for (int mt = 0; mt < 2; mt++)
#pragma unroll
                for (int nt = 0; nt < 8; nt++) {
                    int row = rbase + mt*16 + qr;
                    int col = wn*64 + nt*8 + qc;
                    *(float2*)&Ysh[row*EROW + col]     = make_float2(acc[mt][nt][0], acc[mt][nt][1]);
                    *(float2*)&Ysh[(row+8)*EROW + col] = make_float2(acc[mt][nt][2], acc[mt][nt][3]);
                }
        }
        __syncthreads();
#pragma unroll
        for (int i = 0; i < 8; i++) {
            int e = i*512 + tid;
            int row = e >> 6, c4 = e & 63;
            float4 v = *(const float4*)&Ysh[row*EROW + c4*4];
            *(float4*)&out[(size_t)LOGITS_OFF + (size_t)(t0 + h*64 + row)*DM + n0 + c4*4] = v;
        }
    }
}

// ---------------- activation epilogue ----------------
__device__ __forceinline__ float gelu_exact(float y) {
    return 0.5f * y * (1.0f + erff(y * 0.70710678118654752f));
}
__device__ __forceinline__ float fixv(float v) {
    if (isnan(v)) return 0.f;
    if (isinf(v)) return v > 0.f ? 1000000.0f : -1000000.0f;
    return v;
}

// LN pass: warp-per-16-rows, no block syncs. qbias + GELU + LN + nan_to_num + pool.
__global__ __launch_bounds__(256) void kt_ln(const float* __restrict__ gamma,
                                             const float* __restrict__ beta,
                                             float* __restrict__ out) {
    const int tid = threadIdx.x, lane = tid & 31, wid = tid >> 5;
    const int wg = blockIdx.x * 8 + wid;
    const int t0 = wg * 16;
    float pool[8][4];
#pragma unroll
    for (int j = 0; j < 8; j++)
#pragma unroll
        for (int q = 0; q < 4; q++) pool[j][q] = 0.f;

    for (int r = 0; r < 16; r++) {
        int t = t0 + r;
        int l = t & (NL-1);
        int s = l < NTAP-1 ? l : NTAP-1;
        size_t o = (size_t)LOGITS_OFF + (size_t)t*DM + lane*4;
        float4 v[8];
        float s1 = 0.f, s2 = 0.f;
#pragma unroll
        for (int j = 0; j < 8; j++) {
            float4 y = *(const float4*)&out[o + j*128];
            float4 q = *(const float4*)&g_qb[s*DM + j*128 + lane*4];
            v[j].x = gelu_exact(y.x + q.x);
            v[j].y = gelu_exact(y.y + q.y);
            v[j].z = gelu_exact(y.z + q.z);
            v[j].w = gelu_exact(y.w + q.w);
            s1 += v[j].x + v[j].y + v[j].z + v[j].w;
            s2 += v[j].x*v[j].x + v[j].y*v[j].y + v[j].z*v[j].z + v[j].w*v[j].w;
        }
#pragma unroll
        for (int off = 16; off > 0; off >>= 1) {
            s1 += __shfl_xor_sync(0xffffffffu, s1, off);
            s2 += __shfl_xor_sync(0xffffffffu, s2, off);
        }
        float mu = s1 * (1.0f/DM);
        float rs = rsqrtf(s2 * (1.0f/DM) - mu*mu + 1e-5f);
#pragma unroll
        for (int j = 0; j < 8; j++) {
            float4 g = *(const float4*)&gamma[j*128 + lane*4];
            float4 b = *(const float4*)&beta[j*128 + lane*4];
            float4 nv;
            nv.x = fixv((v[j].x - mu)*rs*g.x + b.x);
            nv.y = fixv((v[j].y - mu)*rs*g.y + b.y);
            nv.z = fixv((v[j].z - mu)*rs*g.z + b.z);
            nv.w = fixv((v[j].w - mu)*rs*g.w + b.w);
            *(float4*)&out[o + j*128] = nv;
            pool[j][0] += nv.x; pool[j][1] += nv.y; pool[j][2] += nv.z; pool[j][3] += nv.w;
        }
    }
    const float inv = 1.0f / (float)NL;
    const int b = t0 >> 10;
#pragma unroll
    for (int j = 0; j < 8; j++) {
        float* pp = &g_pooled[b*DM + j*128 + lane*4];
        atomicAdd(pp+0, pool[j][0]*inv);
        atomicAdd(pp+1, pool[j][1]*inv);
        atomicAdd(pp+2, pool[j][2]*inv);
        atomicAdd(pp+3, pool[j][3]*inv);
    }
}

// ---------------- logits ----------------
__global__ void kt_logits(const float* __restrict__ W_fc, const float* __restrict__ b_fc,
                          float* __restrict__ out) {
    int b = blockIdx.x;
    int lane = threadIdx.x;
    for (int c = 0; c < NCL; c++) {
        float s = 0.f;
        for (int d = lane; d < DM; d += 32)
            s += g_pooled[b*DM + d] * W_fc[c*DM + d];
#pragma unroll
        for (int off = 16; off > 0; off >>= 1)
            s += __shfl_down_sync(0xffffffffu, s, off);
        if (lane == 0) out[b*NCL + c] = s + b_fc[c];
    }
}

// ---------------- launch ----------------
extern "C" void kernel_launch(void* const* d_in, const int* in_sizes, int n_in,
                              void* d_out, int out_size) {
    const float* x     = (const float*)d_in[0];
    const float* W_in  = (const float*)d_in[1];
    const float* b_in  = (const float*)d_in[2];
    const float* A     = (const float*)d_in[3];
    const float* Bm    = (const float*)d_in[4];
    const float* C     = (const float*)d_in[5];
    const float* gamma = (const float*)d_in[6];
    const float* beta  = (const float*)d_in[7];
    const float* W_fc  = (const float*)d_in[8];
    const float* b_fc  = (const float*)d_in[9];
    float* out = (float*)d_out;

    float *pG, *pG2, *pG4, *pM, *pR, *pCT, *pQ, *pBW, *pQB;
    cudaGetSymbolAddress((void**)&pG,  g_G);
    cudaGetSymbolAddress((void**)&pG2, g_G2);
    cudaGetSymbolAddress((void**)&pG4, g_G4);
    cudaGetSymbolAddress((void**)&pM,  g_M);
    cudaGetSymbolAddress((void**)&pR,  g_R);
    cudaGetSymbolAddress((void**)&pCT, g_CT);
    cudaGetSymbolAddress((void**)&pQ,  g_Q);
    cudaGetSymbolAddress((void**)&pBW, g_bw);
    cudaGetSymbolAddress((void**)&pQB, g_qb);

    static int inited = 0;
    if (!inited) {
        cudaFuncSetAttribute(kt_mma, cudaFuncAttributeMaxDynamicSharedMemorySize, SMEM_MMA);
        inited = 1;
    }

    // ---- precompute chain ----
    kt_prep<<<1536, 256>>>(A, C);                                   // G, CT, zero pooled
    kt_gemm32<<<dim3(1,8), 256>>>(pM, Bm, W_in, DS, NIN, DM);
    kt_transpose<<<DS*NIN/256 + 1, 256>>>(pR, pM, DS, NIN);
    kt_gemm32<<<dim3(8,8), 256>>>(pG2, pG, pG, DS, DS, DS);
    kt_gemm32<<<dim3(8,8), 256>>>(pG4, pG2, pG2, DS, DS, DS);
    kt_gemm32<<<dim3(8,1), 256>>>(pR + 1*NIN*DS, pR, pG,  NIN, DS, DS);
    kt_gemm32<<<dim3(8,1), 256>>>(pR + 2*NIN*DS, pR, pG2, NIN, DS, DS);
    kt_gemm32<<<dim3(8,1), 256>>>(pR + 3*NIN*DS, pR + 1*NIN*DS, pG2, NIN, DS, DS);
    kt_gemm32<<<dim3(8,4), 256>>>(pR + 4*NIN*DS, pR, pG4, 4*NIN, DS, DS);
    kt_gemm32<<<dim3(32,7), 256>>>(pQ, pR, pCT, KTOT, DM, DS);
    kt_bvbias<<<1, DS>>>(Bm, b_in);
    kt_gemm32<<<dim3(32,1), 256>>>(pQB, pBW, pCT, NTAP, DM, DS);

    // ---- bf16 split prep ----
    kt_splitX<<<(int)(((size_t)NT*KPAD + 255)/256), 256>>>(x);
    kt_splitQT<<<(DM*KPAD + 255)/256, 256>>>();

    // ---- fused-split tensor-core GEMM + LN + logits ----
    kt_mma<<<(NT/128)*4, 512, SMEM_MMA>>>(out);
    kt_ln<<<NT/128, 256>>>(gamma, beta, out);
    kt_logits<<<NB, 32>>>(W_fc, b_fc, out);
}